// round 1
// baseline (speedup 1.0000x reference)
#include <cuda_runtime.h>
#include <cuda_bf16.h>

// Problem constants
#define KLEN     8192
#define PAIRS    256        // 32 batch * 8 heads
#define DH       64
#define DSTRIDE  16384      // 32*512 floats between consecutive j rows
#define SSPLIT   16         // split-K factor
#define CHUNK    (KLEN / SSPLIT)   // 512 rows per CTA
#define NWARP    8
#define NTHR     (NWARP * 32)

// Partial accumulators (scratch; no allocations allowed)
__device__ float g_num[SSPLIT * PAIRS * DH];
__device__ float g_den[SSPLIT * PAIRS];

__global__ __launch_bounds__(NTHR) void attn_partial(
    const float* __restrict__ q,
    const float* __restrict__ k,
    const float* __restrict__ v)
{
    const int split = blockIdx.x;
    const int pair  = blockIdx.y;
    const int tid   = threadIdx.x;
    const int warp  = tid >> 5;
    const int lane  = tid & 31;
    const int half  = lane >> 4;   // which of the warp's 2 rows
    const int l16   = lane & 15;   // position within a 16-lane row group

    // q slice for this (b,h): 64 contiguous floats at pair*64
    const float4 qv = reinterpret_cast<const float4*>(q + pair * DH)[l16];

    const float* kbase = k + pair * DH + l16 * 4;
    const float* vbase = v + pair * DH + l16 * 4;

    const int jbase = split * CHUNK;

    float4 acc = make_float4(0.f, 0.f, 0.f, 0.f);
    float  den = 0.f;

    // Each CTA-iteration covers 16 consecutive rows; warp w owns rows {2w, 2w+1}.
    #pragma unroll 4
    for (int it = 0; it < CHUNK / 16; ++it) {
        const long j = jbase + it * 16 + warp * 2 + half;
        const float4 kk = *reinterpret_cast<const float4*>(kbase + j * DSTRIDE);
        float d = kk.x * qv.x + kk.y * qv.y + kk.z * qv.z + kk.w * qv.w;
        // reduce over the 16-lane group
        d += __shfl_xor_sync(0xffffffffu, d, 1);
        d += __shfl_xor_sync(0xffffffffu, d, 2);
        d += __shfl_xor_sync(0xffffffffu, d, 4);
        d += __shfl_xor_sync(0xffffffffu, d, 8);
        // clipped score -> weight (bounded in [e^-10, e^10]: no max-tracking needed)
        const float w = __expf(10.0f * tanhf(d * 0.125f));
        const float4 vv = *reinterpret_cast<const float4*>(vbase + j * DSTRIDE);
        acc.x += w * vv.x;
        acc.y += w * vv.y;
        acc.z += w * vv.z;
        acc.w += w * vv.w;
        den   += w;
    }

    // Fold the two 16-lane halves (they hold the same output dims)
    acc.x += __shfl_xor_sync(0xffffffffu, acc.x, 16);
    acc.y += __shfl_xor_sync(0xffffffffu, acc.y, 16);
    acc.z += __shfl_xor_sync(0xffffffffu, acc.z, 16);
    acc.w += __shfl_xor_sync(0xffffffffu, acc.w, 16);
    den   += __shfl_xor_sync(0xffffffffu, den,   16);

    // Cross-warp reduction in shared memory
    __shared__ float s_num[NWARP][DH];
    __shared__ float s_den[NWARP];
    if (half == 0) {
        reinterpret_cast<float4*>(s_num[warp])[l16] = acc;
        if (l16 == 0) s_den[warp] = den;
    }
    __syncthreads();

    if (tid < DH) {
        float n = 0.f;
        #pragma unroll
        for (int w = 0; w < NWARP; ++w) n += s_num[w][tid];
        g_num[(split * PAIRS + pair) * DH + tid] = n;
    }
    if (tid == 0) {
        float dsum = 0.f;
        #pragma unroll
        for (int w = 0; w < NWARP; ++w) dsum += s_den[w];
        g_den[split * PAIRS + pair] = dsum;
    }
}

__global__ void attn_combine(float* __restrict__ out)
{
    const int pair = blockIdx.x;
    const int d    = threadIdx.x;
    float num = 0.f, den = 0.f;
    #pragma unroll
    for (int s = 0; s < SSPLIT; ++s) {
        num += g_num[(s * PAIRS + pair) * DH + d];
        den += g_den[s * PAIRS + pair];
    }
    out[pair * DH + d] = num / den;
}

extern "C" void kernel_launch(void* const* d_in, const int* in_sizes, int n_in,
                              void* d_out, int out_size)
{
    const float* q = (const float*)d_in[0];
    const float* k = (const float*)d_in[1];
    const float* v = (const float*)d_in[2];
    float* out = (float*)d_out;

    dim3 grid(SSPLIT, PAIRS);
    attn_partial<<<grid, NTHR>>>(q, k, v);
    attn_combine<<<PAIRS, DH>>>(out);
}